// round 7
// baseline (speedup 1.0000x reference)
#include <cuda_runtime.h>
#include <cuda_bf16.h>
#include <cstdint>

#define SEQ 386
#define NP  385
#define HH  256
#define EMB 128
#define G4  1024
#define OSTR (385*129)

typedef unsigned long long ull;

__device__ float g_emb[SEQ][EMB];
__device__ float g_xpre[2][SEQ][G4];
__device__ float g_h[2][SEQ][HH];
__device__ float g_U[NP][HH];
__device__ float g_V[NP][HH];

__device__ __forceinline__ ull pack2(float lo, float hi) {
    ull r; asm("mov.b64 %0, {%1, %2};" : "=l"(r) : "f"(lo), "f"(hi)); return r;
}
__device__ __forceinline__ void unpack2(ull v, float& lo, float& hi) {
    asm("mov.b64 {%0, %1}, %2;" : "=f"(lo), "=f"(hi) : "l"(v));
}
__device__ __forceinline__ void ffma2(ull& d, ull a, ull b) {
    asm("fma.rn.f32x2 %0, %1, %2, %0;" : "+l"(d) : "l"(a), "l"(b));
}
__device__ __forceinline__ unsigned smem_u32(const void* p) {
    unsigned a;
    asm("{ .reg .u64 t; cvta.to.shared.u64 t, %1; cvt.u32.u64 %0, t; }" : "=r"(a) : "l"(p));
    return a;
}
__device__ __forceinline__ void st_cluster(unsigned addr, int rank, float v) {
    unsigned ra;
    asm volatile("mapa.shared::cluster.u32 %0, %1, %2;" : "=r"(ra) : "r"(addr), "r"(rank));
    asm volatile("st.shared::cluster.f32 [%0], %1;" :: "r"(ra), "f"(v) : "memory");
}
__device__ __forceinline__ void cluster_sync_() {
    asm volatile("barrier.cluster.arrive.aligned;" ::: "memory");
    asm volatile("barrier.cluster.wait.aligned;" ::: "memory");
}
__device__ __forceinline__ float sigx(float x)  { return 1.f / (1.f + __expf(-x)); }
__device__ __forceinline__ float tanhx(float x) { return 2.f / (1.f + __expf(-2.f * x)) - 1.f; }

// ---------- K1: embeddings ----------
__global__ void k_embed(const int* __restrict__ tg, const int* __restrict__ wd,
                        const float* __restrict__ te, const float* __restrict__ we) {
    int t = blockIdx.x, d = threadIdx.x;
    g_emb[t][d] = te[tg[t] * EMB + d] + we[wd[t] * EMB + d];
}

// ---------- K2: x preactivations ----------
__global__ void __launch_bounds__(1024, 1)
k_xpre(const float* __restrict__ wxf, const float* __restrict__ bfp,
       const float* __restrict__ wxb, const float* __restrict__ bbp) {
    __shared__ float se[8][128];
    int tid = threadIdx.x, t0 = blockIdx.x * 8, dir = blockIdx.y;
    for (int idx = tid; idx < 1024; idx += 1024) {
        int tp = idx >> 7, d = idx & 127, t = t0 + tp;
        se[tp][d] = (t < SEQ) ? g_emb[t][d] : 0.f;
    }
    __syncthreads();
    const float* Wx = dir ? wxb : wxf;
    const float* bp = dir ? bbp : bfp;
    float acc[8] = {0, 0, 0, 0, 0, 0, 0, 0};
    const float4* wr = (const float4*)(Wx + tid * 128);
    for (int d4 = 0; d4 < 32; ++d4) {
        float4 w = wr[d4];
        int d = d4 * 4;
#pragma unroll
        for (int tp = 0; tp < 8; ++tp)
            acc[tp] += w.x * se[tp][d] + w.y * se[tp][d + 1] + w.z * se[tp][d + 2] + w.w * se[tp][d + 3];
    }
    float bias = bp[tid];
#pragma unroll
    for (int tp = 0; tp < 8; ++tp) {
        int t = t0 + tp;
        if (t < SEQ) g_xpre[dir][t][tid] = acc[tp] + bias;
    }
}

// ---------- K3: BiLSTM, cluster of 8 CTAs per direction ----------
__global__ void __cluster_dims__(8, 1, 1) __launch_bounds__(512, 1)
k_lstm(const float* __restrict__ whf, const float* __restrict__ whb) {
    __shared__ float hbuf[2][HH];
    int tid = threadIdx.x;
    int dir = blockIdx.x >> 3, rank = blockIdx.x & 7;
    int ql = tid >> 4, gt = (tid >> 2) & 3, p = tid & 3, lane = tid & 31;
    int row = gt * 256 + rank * 32 + ql;
    const float* Wh = dir ? whb : whf;

    ull w[32];
#pragma unroll
    for (int it = 0; it < 32; ++it) {
        int k0 = (p << 6) | ((2 * it + 8 * p) & 63);
        w[it] = pack2(Wh[row * 256 + k0], Wh[row * 256 + k0 + 1]);
    }
    ((float*)hbuf)[tid] = 0.f;   // zeroes both 256-float buffers
    __syncthreads();
    cluster_sync_();

    float c_state = 0.f;
    int t = dir ? (SEQ - 1) : 0;
    float xcur = g_xpre[dir][t][row];

    for (int s = 0; s < SEQ; ++s) {
        int cur = s & 1, nxt = cur ^ 1;
        int tn = dir ? (SEQ - 2 - s) : (s + 1);
        float xnext = (s < SEQ - 1) ? g_xpre[dir][tn][row] : 0.f;

        ull acc = 0ULL;
#pragma unroll
        for (int it = 0; it < 32; ++it) {
            int k0 = (p << 6) | ((2 * it + 8 * p) & 63);
            ffma2(acc, w[it], *(const ull*)&hbuf[cur][k0]);
        }
        float a, b; unpack2(acc, a, b);
        float r = a + b;
        r += __shfl_xor_sync(0xffffffffu, r, 1);
        r += __shfl_xor_sync(0xffffffffu, r, 2);
        float pre = r + xcur;

        int base = lane & 16;
        float pi = __shfl_sync(0xffffffffu, pre, base);
        float pf = __shfl_sync(0xffffffffu, pre, base + 4);
        float pg = __shfl_sync(0xffffffffu, pre, base + 8);
        float po = __shfl_sync(0xffffffffu, pre, base + 12);

        if ((lane & 15) == 0) {
            c_state = sigx(pf) * c_state + sigx(pi) * tanhx(pg);
            float hv = sigx(po) * tanhx(c_state);
            int q = rank * 32 + ql;
            g_h[dir][t][q] = hv;
            unsigned la = smem_u32(&hbuf[nxt][q]);
#pragma unroll
            for (int rr = 0; rr < 8; ++rr) st_cluster(la, rr, hv);
        }
        cluster_sync_();
        t = tn;
        xcur = xnext;
    }
}

// ---------- K4: U/V span transforms ----------
__global__ void __launch_bounds__(256, 1)
k_uv(const float* __restrict__ lab_w1, const float* __restrict__ spl_w1) {
    __shared__ float sh[4][516];
    int tid = threadIdx.x, k0 = blockIdx.x * 4, which = blockIdx.y;
    for (int idx = tid; idx < 2048; idx += 256) {
        int kk = idx >> 9, d = idx & 511, k = k0 + kk;
        float v = 0.f;
        if (k < NP) v = (d < 256) ? g_h[0][k][d] : -g_h[1][k + 1][d - 256];
        sh[kk][d] = v;
    }
    __syncthreads();
    const float* w1 = which ? spl_w1 : lab_w1;
    float a0 = 0, a1 = 0, a2 = 0, a3 = 0;
    const float4* wr = (const float4*)(w1 + tid * 512);
    for (int d4 = 0; d4 < 128; ++d4) {
        float4 wv = wr[d4];
        int d = d4 * 4;
        a0 += wv.x * sh[0][d] + wv.y * sh[0][d + 1] + wv.z * sh[0][d + 2] + wv.w * sh[0][d + 3];
        a1 += wv.x * sh[1][d] + wv.y * sh[1][d + 1] + wv.z * sh[1][d + 2] + wv.w * sh[1][d + 3];
        a2 += wv.x * sh[2][d] + wv.y * sh[2][d + 1] + wv.z * sh[2][d + 2] + wv.w * sh[2][d + 3];
        a3 += wv.x * sh[3][d] + wv.y * sh[3][d + 1] + wv.z * sh[3][d + 2] + wv.w * sh[3][d + 3];
    }
    float (*dst)[HH] = which ? g_V : g_U;
    if (k0     < NP) dst[k0    ][tid] = a0;
    if (k0 + 1 < NP) dst[k0 + 1][tid] = a1;
    if (k0 + 2 < NP) dst[k0 + 2][tid] = a2;
    if (k0 + 3 < NP) dst[k0 + 3][tid] = a3;
}

// ---------- K5: pairwise outputs ----------
// block = 4 i x 16 j = 64 pairs. smem: W2P [256][64] ull (128KB),
// HID [256][64] f32 (64KB), SW2[256], LB2[128].
__global__ void __launch_bounds__(256, 1)
k_out(const float* __restrict__ lab_b1, const float* __restrict__ lab_w2,
      const float* __restrict__ lab_b2, const float* __restrict__ spl_b1,
      const float* __restrict__ spl_w2, const float* __restrict__ spl_b2,
      float* __restrict__ out) {
    extern __shared__ char sm[];
    ull*   W2P = (ull*)sm;
    float* HID = (float*)(sm + 131072);
    float* SW2 = HID + 256 * 64;
    float* LB2 = SW2 + 256;
    int tid = threadIdx.x;
    int j0 = blockIdx.x * 16, i0 = blockIdx.y * 4;

    for (int idx = tid; idx < 256 * 64; idx += 256) {
        int k = idx >> 6, cp = idx & 63;
        W2P[k * 64 + cp] = pack2(lab_w2[(2 * cp) * 256 + k], lab_w2[(2 * cp + 1) * 256 + k]);
    }
    SW2[tid] = spl_w2[tid];
    if (tid < 128) LB2[tid] = lab_b2[tid];
    __syncthreads();

    // phase A: hidden tiles + split head
    {
        int pr = tid >> 2, kg = tid & 3;
        int il = pr >> 4, jl = pr & 15;
        int i = min(i0 + il, NP - 1), j = min(j0 + jl, NP - 1);
        const float* Uj = g_U[j]; const float* Ui = g_U[i];
        const float* Vj = g_V[j]; const float* Vi = g_V[i];
        float sacc = 0.f;
        int kb = kg * 64;
        for (int kk = 0; kk < 64; ++kk) {
            int k = kb + kk;
            HID[k * 64 + pr] = fmaxf(Uj[k] - Ui[k] + lab_b1[k], 0.f);
            sacc += fmaxf(Vj[k] - Vi[k] + spl_b1[k], 0.f) * SW2[k];
        }
        sacc += __shfl_xor_sync(0xffffffffu, sacc, 1);
        sacc += __shfl_xor_sync(0xffffffffu, sacc, 2);
        if (kg == 0 && i0 + il < NP && j0 + jl < NP)
            out[(i0 + il) * OSTR + (j0 + jl) * 129 + 128] = sacc + spl_b2[0];
    }
    __syncthreads();

    // phase B: label GEMM, 4 pairs x 4 c-pairs per thread
    int pg = tid >> 4, cg = tid & 15;
    ull acc[4][4];
#pragma unroll
    for (int a = 0; a < 4; ++a)
#pragma unroll
        for (int b = 0; b < 4; ++b) acc[a][b] = 0ULL;

    const float* hb = HID + pg * 4;
    const ull*  wb = W2P + cg * 4;
    for (int k = 0; k < 256; ++k) {
        float4 h4 = *(const float4*)(hb + k * 64);
        ull h0 = pack2(h4.x, h4.x), h1 = pack2(h4.y, h4.y);
        ull h2 = pack2(h4.z, h4.z), h3 = pack2(h4.w, h4.w);
        ull w0 = wb[k * 64], w1 = wb[k * 64 + 1], w2 = wb[k * 64 + 2], w3 = wb[k * 64 + 3];
        ffma2(acc[0][0], h0, w0); ffma2(acc[0][1], h0, w1); ffma2(acc[0][2], h0, w2); ffma2(acc[0][3], h0, w3);
        ffma2(acc[1][0], h1, w0); ffma2(acc[1][1], h1, w1); ffma2(acc[1][2], h1, w2); ffma2(acc[1][3], h1, w3);
        ffma2(acc[2][0], h2, w0); ffma2(acc[2][1], h2, w1); ffma2(acc[2][2], h2, w2); ffma2(acc[2][3], h2, w3);
        ffma2(acc[3][0], h3, w0); ffma2(acc[3][1], h3, w1); ffma2(acc[3][2], h3, w2); ffma2(acc[3][3], h3, w3);
    }
#pragma unroll
    for (int pp = 0; pp < 4; ++pp) {
        int pr = pg * 4 + pp;
        int i = i0 + (pr >> 4), j = j0 + (pr & 15);
        if (i >= NP || j >= NP) continue;
        float* o = out + i * OSTR + j * 129;
#pragma unroll
        for (int q = 0; q < 4; ++q) {
            int c = (cg * 4 + q) * 2;
            float lo, hi; unpack2(acc[pp][q], lo, hi);
            o[c]     = lo + LB2[c];
            o[c + 1] = hi + LB2[c + 1];
        }
    }
}

extern "C" void kernel_launch(void* const* d_in, const int* in_sizes, int n_in,
                              void* d_out, int out_size) {
    const int*   tag_ids  = (const int*)d_in[0];
    const int*   word_ids = (const int*)d_in[1];
    const float* tag_emb  = (const float*)d_in[2];
    const float* word_emb = (const float*)d_in[3];
    const float* wxf = (const float*)d_in[4];
    const float* whf = (const float*)d_in[5];
    const float* bf  = (const float*)d_in[6];
    const float* wxb = (const float*)d_in[7];
    const float* whb = (const float*)d_in[8];
    const float* bb  = (const float*)d_in[9];
    const float* lab_w1 = (const float*)d_in[10];
    const float* lab_b1 = (const float*)d_in[11];
    const float* lab_w2 = (const float*)d_in[12];
    const float* lab_b2 = (const float*)d_in[13];
    const float* spl_w1 = (const float*)d_in[14];
    const float* spl_b1 = (const float*)d_in[15];
    const float* spl_w2 = (const float*)d_in[16];
    const float* spl_b2 = (const float*)d_in[17];
    float* out = (float*)d_out;

    static int smem_set = 0;
    if (!smem_set) {
        cudaFuncSetAttribute(k_out, cudaFuncAttributeMaxDynamicSharedMemorySize, 198144);
        smem_set = 1;
    }

    k_embed<<<SEQ, EMB>>>(tag_ids, word_ids, tag_emb, word_emb);
    k_xpre<<<dim3(49, 2), 1024>>>(wxf, bf, wxb, bb);
    k_lstm<<<16, 512>>>(whf, whb);
    k_uv<<<dim3(97, 2), 256>>>(lab_w1, spl_w1);
    k_out<<<dim3(25, 97), 256, 198144>>>(lab_b1, lab_w2, lab_b2, spl_b1, spl_w2, spl_b2, out);
}

// round 8
// speedup vs baseline: 1.7098x; 1.7098x over previous
#include <cuda_runtime.h>
#include <cuda_bf16.h>
#include <cstdint>

#define SEQ 386
#define NP  385
#define HH  256
#define EMB 128
#define G4  1024
#define OSTR (385*129)

typedef unsigned long long ull;

__device__ float g_emb[SEQ][EMB];
__device__ float g_xpre[2][SEQ][G4];
__device__ float g_h[2][SEQ][HH];
__device__ float g_U[NP][HH];
__device__ float g_V[NP][HH];
__device__ ull   g_w2p[256 * 64];   // [k][cpair] packed label w2

__device__ __forceinline__ ull pack2(float lo, float hi) {
    ull r; asm("mov.b64 %0, {%1, %2};" : "=l"(r) : "f"(lo), "f"(hi)); return r;
}
__device__ __forceinline__ void unpack2(ull v, float& lo, float& hi) {
    asm("mov.b64 {%0, %1}, %2;" : "=f"(lo), "=f"(hi) : "l"(v));
}
__device__ __forceinline__ void ffma2(ull& d, ull a, ull b) {
    asm("fma.rn.f32x2 %0, %1, %2, %0;" : "+l"(d) : "l"(a), "l"(b));
}
__device__ __forceinline__ unsigned smem_u32(const void* p) {
    unsigned a;
    asm("{ .reg .u64 t; cvta.to.shared.u64 t, %1; cvt.u32.u64 %0, t; }" : "=r"(a) : "l"(p));
    return a;
}
__device__ __forceinline__ void st_cluster(unsigned addr, int rank, float v) {
    unsigned ra;
    asm volatile("mapa.shared::cluster.u32 %0, %1, %2;" : "=r"(ra) : "r"(addr), "r"(rank));
    asm volatile("st.shared::cluster.f32 [%0], %1;" :: "r"(ra), "f"(v) : "memory");
}
__device__ __forceinline__ void cluster_sync_() {
    asm volatile("barrier.cluster.arrive.aligned;" ::: "memory");
    asm volatile("barrier.cluster.wait.aligned;" ::: "memory");
}
__device__ __forceinline__ float sigx(float x)  { return 1.f / (1.f + __expf(-x)); }
__device__ __forceinline__ float tanhx(float x) { return 2.f / (1.f + __expf(-2.f * x)) - 1.f; }

// ---------- K1: embeddings ----------
__global__ void k_embed(const int* __restrict__ tg, const int* __restrict__ wd,
                        const float* __restrict__ te, const float* __restrict__ we) {
    int t = blockIdx.x, d = threadIdx.x;
    g_emb[t][d] = te[tg[t] * EMB + d] + we[wd[t] * EMB + d];
}

// ---------- K1b: pack label w2 into [k][cpair] (run once per launch) ----------
__global__ void k_w2pack(const float* __restrict__ lab_w2) {
    int idx = blockIdx.x * 256 + threadIdx.x;      // 0..16383
    int cp = idx >> 8, k = idx & 255;
    g_w2p[k * 64 + cp] = pack2(lab_w2[(2 * cp) * 256 + k], lab_w2[(2 * cp + 1) * 256 + k]);
}

// ---------- K2: x preactivations (Wx staged through smem, coalesced) ----------
__global__ void __launch_bounds__(1024, 1)
k_xpre(const float* __restrict__ wxf, const float* __restrict__ bfp,
       const float* __restrict__ wxb, const float* __restrict__ bbp) {
    __shared__ float se[8][128];
    __shared__ float wt[1024][9];
    int tid = threadIdx.x, t0 = blockIdx.x * 8, dir = blockIdx.y;
    {
        int tp = tid >> 7, d = tid & 127, t = t0 + tp;
        se[tp][d] = (t < SEQ) ? g_emb[t][d] : 0.f;
    }
    const float* Wx = dir ? wxb : wxf;
    const float* bp = dir ? bbp : bfp;
    float acc[8] = {0, 0, 0, 0, 0, 0, 0, 0};
    for (int d0 = 0; d0 < 128; d0 += 8) {
        __syncthreads();
#pragma unroll
        for (int it = 0; it < 8; ++it) {
            int idx = tid + it * 1024;
            int row = idx >> 3, dd = idx & 7;
            wt[row][dd] = Wx[row * 128 + d0 + dd];
        }
        __syncthreads();
#pragma unroll
        for (int dd = 0; dd < 8; ++dd) {
            float w = wt[tid][dd];
#pragma unroll
            for (int tp = 0; tp < 8; ++tp) acc[tp] += w * se[tp][d0 + dd];
        }
    }
    float bias = bp[tid];
#pragma unroll
    for (int tp = 0; tp < 8; ++tp) {
        int t = t0 + tp;
        if (t < SEQ) g_xpre[dir][t][tid] = acc[tp] + bias;
    }
}

// ---------- K3: BiLSTM, cluster of 8 CTAs per direction (unchanged) ----------
__global__ void __cluster_dims__(8, 1, 1) __launch_bounds__(512, 1)
k_lstm(const float* __restrict__ whf, const float* __restrict__ whb) {
    __shared__ float hbuf[2][HH];
    int tid = threadIdx.x;
    int dir = blockIdx.x >> 3, rank = blockIdx.x & 7;
    int ql = tid >> 4, gt = (tid >> 2) & 3, p = tid & 3, lane = tid & 31;
    int row = gt * 256 + rank * 32 + ql;
    const float* Wh = dir ? whb : whf;

    ull w[32];
#pragma unroll
    for (int it = 0; it < 32; ++it) {
        int k0 = (p << 6) | ((2 * it + 8 * p) & 63);
        w[it] = pack2(Wh[row * 256 + k0], Wh[row * 256 + k0 + 1]);
    }
    ((float*)hbuf)[tid] = 0.f;
    __syncthreads();
    cluster_sync_();

    float c_state = 0.f;
    int t = dir ? (SEQ - 1) : 0;
    float xcur = g_xpre[dir][t][row];

    for (int s = 0; s < SEQ; ++s) {
        int cur = s & 1, nxt = cur ^ 1;
        int tn = dir ? (SEQ - 2 - s) : (s + 1);
        float xnext = (s < SEQ - 1) ? g_xpre[dir][tn][row] : 0.f;

        ull acc = 0ULL;
#pragma unroll
        for (int it = 0; it < 32; ++it) {
            int k0 = (p << 6) | ((2 * it + 8 * p) & 63);
            ffma2(acc, w[it], *(const ull*)&hbuf[cur][k0]);
        }
        float a, b; unpack2(acc, a, b);
        float r = a + b;
        r += __shfl_xor_sync(0xffffffffu, r, 1);
        r += __shfl_xor_sync(0xffffffffu, r, 2);
        float pre = r + xcur;

        int base = lane & 16;
        float pi = __shfl_sync(0xffffffffu, pre, base);
        float pf = __shfl_sync(0xffffffffu, pre, base + 4);
        float pg = __shfl_sync(0xffffffffu, pre, base + 8);
        float po = __shfl_sync(0xffffffffu, pre, base + 12);

        if ((lane & 15) == 0) {
            c_state = sigx(pf) * c_state + sigx(pi) * tanhx(pg);
            float hv = sigx(po) * tanhx(c_state);
            int q = rank * 32 + ql;
            g_h[dir][t][q] = hv;
            unsigned la = smem_u32(&hbuf[nxt][q]);
#pragma unroll
            for (int rr = 0; rr < 8; ++rr) st_cluster(la, rr, hv);
        }
        cluster_sync_();
        t = tn;
        xcur = xnext;
    }
}

// ---------- K4: U/V span transforms (warp-per-channel, coalesced w1) ----------
__global__ void __launch_bounds__(256, 1)
k_uv(const float* __restrict__ lab_w1, const float* __restrict__ spl_w1) {
    __shared__ float sh2[512][2];
    int tid = threadIdx.x, k0 = blockIdx.x * 2, which = blockIdx.y;
    for (int idx = tid; idx < 1024; idx += 256) {
        int d = idx >> 1, kk = idx & 1, k = k0 + kk;
        float v = 0.f;
        if (k < NP) v = (d < 256) ? g_h[0][k][d] : -g_h[1][k + 1][d - 256];
        sh2[d][kk] = v;
    }
    __syncthreads();
    const float* w1 = which ? spl_w1 : lab_w1;
    int w = tid >> 5, lane = tid & 31;
    float (*dst)[HH] = which ? g_V : g_U;
#pragma unroll 2
    for (int cx = 0; cx < 32; ++cx) {
        int c = w * 32 + cx;
        const float* wr = w1 + c * 512;
        ull acc = 0ULL;
#pragma unroll
        for (int m = 0; m < 16; ++m) {
            int d = m * 32 + lane;
            float wv = wr[d];
            ffma2(acc, pack2(wv, wv), *(const ull*)&sh2[d][0]);
        }
        float a, b; unpack2(acc, a, b);
#pragma unroll
        for (int off = 16; off; off >>= 1) {
            a += __shfl_xor_sync(0xffffffffu, a, off);
            b += __shfl_xor_sync(0xffffffffu, b, off);
        }
        if (lane == 0) {
            if (k0     < NP) dst[k0    ][c] = a;
            if (k0 + 1 < NP) dst[k0 + 1][c] = b;
        }
    }
}

// ---------- K5: pairwise outputs ----------
// block = 4 i x 16 j = 64 pairs; 256 threads.
// smem: W2P ull[256][64] (128KB) + HID2 float[64][260] (65KB) + consts.
#define HIDSTR 260
#define SM_HID   131072
#define SM_LB1   (SM_HID + 64 * HIDSTR * 4)
#define SM_SB1   (SM_LB1 + 1024)
#define SM_SW2   (SM_SB1 + 1024)
#define SM_LB2   (SM_SW2 + 1024)
#define SM_TOTAL (SM_LB2 + 512)

__global__ void __launch_bounds__(256, 1)
k_out(const float* __restrict__ lab_b1, const float* __restrict__ lab_b2,
      const float* __restrict__ spl_b1, const float* __restrict__ spl_w2,
      const float* __restrict__ spl_b2, float* __restrict__ out) {
    extern __shared__ char sm[];
    ull*   W2P  = (ull*)sm;
    float* HID2 = (float*)(sm + SM_HID);
    float* LB1  = (float*)(sm + SM_LB1);
    float* SB1  = (float*)(sm + SM_SB1);
    float* SW2  = (float*)(sm + SM_SW2);
    float* LB2  = (float*)(sm + SM_LB2);
    int tid = threadIdx.x;
    int j0 = blockIdx.x * 16, i0 = blockIdx.y * 4;

    {   // coalesced stage of packed w2 (128KB)
        const float4* src = (const float4*)g_w2p;
        float4* dst = (float4*)W2P;
        for (int it = tid; it < 8192; it += 256) dst[it] = src[it];
    }
    LB1[tid] = lab_b1[tid];
    SB1[tid] = spl_b1[tid];
    SW2[tid] = spl_w2[tid];
    if (tid < 128) LB2[tid] = lab_b2[tid];
    __syncthreads();

    // ---- phase A: hidden tiles (coalesced, warp-per-pair) + split head ----
    int wp = tid >> 5, lane = tid & 31;
    float sb2 = spl_b2[0];
    for (int px = 0; px < 8; ++px) {
        int p = wp * 8 + px;
        int i = i0 + (p >> 4), j = j0 + (p & 15);
        int ic = min(i, NP - 1), jc = min(j, NP - 1);
        const float* Uj = g_U[jc]; const float* Ui = g_U[ic];
        const float* Vj = g_V[jc]; const float* Vi = g_V[ic];
        float sacc = 0.f;
#pragma unroll
        for (int m = 0; m < 8; ++m) {
            int k = m * 32 + lane;
            HID2[p * HIDSTR + k] = fmaxf(Uj[k] - Ui[k] + LB1[k], 0.f);
            sacc += fmaxf(Vj[k] - Vi[k] + SB1[k], 0.f) * SW2[k];
        }
#pragma unroll
        for (int off = 16; off; off >>= 1)
            sacc += __shfl_xor_sync(0xffffffffu, sacc, off);
        if (lane == 0 && i < NP && j < NP)
            out[i * OSTR + j * 129 + 128] = sacc + sb2;
    }
    __syncthreads();

    // ---- phase B: label GEMM, 4 pairs x 4 c-pairs per thread ----
    int pg = tid >> 4, cg = tid & 15;
    ull acc[4][4];
#pragma unroll
    for (int a = 0; a < 4; ++a)
#pragma unroll
        for (int b = 0; b < 4; ++b) acc[a][b] = 0ULL;

    const float* hb = HID2 + pg * 4 * HIDSTR;
    const ull*  wb = W2P + cg;
#pragma unroll 2
    for (int k = 0; k < 256; ++k) {
        float h0 = hb[k], h1 = hb[HIDSTR + k], h2 = hb[2 * HIDSTR + k], h3 = hb[3 * HIDSTR + k];
        ull H0 = pack2(h0, h0), H1 = pack2(h1, h1), H2 = pack2(h2, h2), H3 = pack2(h3, h3);
        ull w0 = wb[k * 64], w1 = wb[k * 64 + 16], w2 = wb[k * 64 + 32], w3 = wb[k * 64 + 48];
        ffma2(acc[0][0], H0, w0); ffma2(acc[0][1], H0, w1); ffma2(acc[0][2], H0, w2); ffma2(acc[0][3], H0, w3);
        ffma2(acc[1][0], H1, w0); ffma2(acc[1][1], H1, w1); ffma2(acc[1][2], H1, w2); ffma2(acc[1][3], H1, w3);
        ffma2(acc[2][0], H2, w0); ffma2(acc[2][1], H2, w1); ffma2(acc[2][2], H2, w2); ffma2(acc[2][3], H2, w3);
        ffma2(acc[3][0], H3, w0); ffma2(acc[3][1], H3, w1); ffma2(acc[3][2], H3, w2); ffma2(acc[3][3], H3, w3);
    }
#pragma unroll
    for (int pp = 0; pp < 4; ++pp) {
        int p = pg * 4 + pp;
        int i = i0 + (p >> 4), j = j0 + (p & 15);
        if (i >= NP || j >= NP) continue;
        float* o = out + i * OSTR + j * 129;
#pragma unroll
        for (int q = 0; q < 4; ++q) {
            int cp = cg + 16 * q;
            float lo, hi; unpack2(acc[pp][q], lo, hi);
            o[2 * cp]     = lo + LB2[2 * cp];
            o[2 * cp + 1] = hi + LB2[2 * cp + 1];
        }
    }
}

extern "C" void kernel_launch(void* const* d_in, const int* in_sizes, int n_in,
                              void* d_out, int out_size) {
    const int*   tag_ids  = (const int*)d_in[0];
    const int*   word_ids = (const int*)d_in[1];
    const float* tag_emb  = (const float*)d_in[2];
    const float* word_emb = (const float*)d_in[3];
    const float* wxf = (const float*)d_in[4];
    const float* whf = (const float*)d_in[5];
    const float* bf  = (const float*)d_in[6];
    const float* wxb = (const float*)d_in[7];
    const float* whb = (const float*)d_in[8];
    const float* bb  = (const float*)d_in[9];
    const float* lab_w1 = (const float*)d_in[10];
    const float* lab_b1 = (const float*)d_in[11];
    const float* lab_w2 = (const float*)d_in[12];
    const float* lab_b2 = (const float*)d_in[13];
    const float* spl_w1 = (const float*)d_in[14];
    const float* spl_b1 = (const float*)d_in[15];
    const float* spl_w2 = (const float*)d_in[16];
    const float* spl_b2 = (const float*)d_in[17];
    float* out = (float*)d_out;

    static int smem_set = 0;
    if (!smem_set) {
        cudaFuncSetAttribute(k_out, cudaFuncAttributeMaxDynamicSharedMemorySize, SM_TOTAL);
        smem_set = 1;
    }

    k_embed<<<SEQ, EMB>>>(tag_ids, word_ids, tag_emb, word_emb);
    k_w2pack<<<64, 256>>>(lab_w2);
    k_xpre<<<dim3(49, 2), 1024>>>(wxf, bf, wxb, bb);
    k_lstm<<<16, 512>>>(whf, whb);
    k_uv<<<dim3(193, 2), 256>>>(lab_w1, spl_w1);
    k_out<<<dim3(25, 97), 256, SM_TOTAL>>>(lab_b1, lab_b2, spl_b1, spl_w2, spl_b2, out);
}